// round 10
// baseline (speedup 1.0000x reference)
#include <cuda_runtime.h>
#include <cstdint>
#include <cstddef>

#define NVEC 1024
#define NDIM 64
#define NHID 32
#define NW   10
#define NB   16
#define NOFF 11

// Scratch (no allocations allowed): device globals.
__device__ float g_w[NW * NB * NOFF * NVEC];   // sparse W values [i][b][o][n]
__device__ float g_H[NW * NB * NVEC * NHID];   // gelu hidden activations (21MB)
__device__ float g_fW2T[NW * NVEC * NHID];     // fW2 transposed [i][n][h]
__device__ float g_fWT3[10 * 16 * NVEC * 4];   // finW as [c][dg][n][4] (2.6MB)
__device__ float g_part[NB * 16 * 10];         // partial sums for output GEMM
__device__ int   g_cnt;                        // block completion counter

// ---------- f32x2 packed helpers (sm_103a FFMA2) ----------
__device__ __forceinline__ unsigned long long pack2(float x, float y) {
    unsigned long long r;
    asm("mov.b64 %0, {%1, %2};" : "=l"(r) : "f"(x), "f"(y));
    return r;
}
__device__ __forceinline__ void fma2(unsigned long long& d, unsigned long long a, unsigned long long b) {
    asm("fma.rn.f32x2 %0, %1, %2, %0;" : "+l"(d) : "l"(a), "l"(b));
}
__device__ __forceinline__ float2 unpack2(unsigned long long v) {
    float lo, hi;
    asm("mov.b64 {%0, %1}, %2;" : "=f"(lo), "=f"(hi) : "l"(v));
    return make_float2(lo, hi);
}
__device__ __forceinline__ float gelu_exact(float x) {
    return 0.5f * x * (1.0f + erff(x * 0.70710678f));
}

// ---------------------------------------------------------------------------
// prep_kernel: 52 blocks x 256 threads.
// blocks [0,20):  fW2 transpose halves -> g_fW2T
// blocks [20,52): finW tiles -> g_fWT3
// ---------------------------------------------------------------------------
__global__ void __launch_bounds__(256) prep_kernel(
    const float* __restrict__ fW2, const float* __restrict__ finW)
{
    __shared__ float sm[2816];            // max(32*33, 256*11)
    const int t = threadIdx.x;

    if (blockIdx.x < 20) {
        const int i  = blockIdx.x >> 1;
        const int c0 = (blockIdx.x & 1) * 512;
        float* tile = sm;                 // [32][33]
        for (int s = 0; s < 16; s++) {
#pragma unroll
            for (int it = 0; it < 4; it++) {
                int r = it * 8 + (t >> 5);
                int c = t & 31;
                tile[r * 33 + c] = fW2[((size_t)(i * NHID) + r) * NVEC + c0 + s * 32 + c];
            }
            __syncthreads();
            int cr = t >> 3, rg = t & 7;
            float4 v = make_float4(tile[(4 * rg + 0) * 33 + cr],
                                   tile[(4 * rg + 1) * 33 + cr],
                                   tile[(4 * rg + 2) * 33 + cr],
                                   tile[(4 * rg + 3) * 33 + cr]);
            *reinterpret_cast<float4*>(
                &g_fW2T[((size_t)(i * NVEC) + c0 + s * 32 + cr) * NHID + 4 * rg]) = v;
            __syncthreads();
        }
        return;
    }

    // finW tiles: [f][10] -> [c][dg][n][4]
    const int idx = blockIdx.x - 20;      // 0..31 -> 2048 f each
    float* sF = sm;                       // [256][11]
    float4* dst = reinterpret_cast<float4*>(g_fWT3);
#pragma unroll 1
    for (int s = 0; s < 8; s++) {
        const int fbase = idx * 2048 + s * 256;
        const int nbase = idx * 32 + s * 4;
        const float4* src =
            reinterpret_cast<const float4*>(finW + (size_t)fbase * 10);
#pragma unroll
        for (int j = 0; j < 3; j++) {
            int p = t + 256 * j;
            if (p < 640) {
                float4 v = __ldg(src + p);
                float vals[4] = {v.x, v.y, v.z, v.w};
#pragma unroll
                for (int u = 0; u < 4; u++) {
                    int e  = 4 * p + u;
                    int fl = e / 10, c = e - 10 * fl;
                    sF[fl * 11 + c] = vals[u];
                }
            }
        }
        __syncthreads();
#pragma unroll
        for (int j = 0; j < 3; j++) {
            int oi = t + 256 * j;
            if (oi < 640) {
                int c  = oi / 64;
                int r  = oi - 64 * c;
                int dg = r >> 2, nn = r & 3;
                float4 v;
                v.x = sF[(nn * 64 + 4 * dg + 0) * 11 + c];
                v.y = sF[(nn * 64 + 4 * dg + 1) * 11 + c];
                v.z = sF[(nn * 64 + 4 * dg + 2) * 11 + c];
                v.w = sF[(nn * 64 + 4 * dg + 3) * 11 + c];
                dst[(c * 16 + dg) * 1024 + nbase + nn] = v;
            }
        }
        __syncthreads();
    }
}

// ---------------------------------------------------------------------------
// Kernel A: H = gelu(X @ fW1 + fb1), 4n x 8h register tile, 256 threads.
// k in 8 chunks of 8, DOUBLE-BUFFERED: LDG for chunk c+1 issued into regs
// before computing chunk c (hides global latency within each warp), STS after.
// Xs[2][256][9] (odd stride -> conflict-free x reads). 26.8KB smem, 4 CTAs/SM.
// Grid exactly 640 = 1.08 waves.
// ---------------------------------------------------------------------------
#define XS 9
#define H_SMEM ((2 * 256 * XS + NDIM * NHID + NHID) * 4)   // 26752 B

__global__ void __launch_bounds__(256, 4) h_kernel(
    const float* __restrict__ data, const float* __restrict__ fW1,
    const float* __restrict__ fb1)
{
    extern __shared__ float sm[];
    float* Xs   = sm;                   // [2][256][9]
    float* sw1  = sm + 2 * 256 * XS;    // [64][32]
    float* sfb1 = sw1 + NDIM * NHID;    // [32]

    const int t  = threadIdx.x;
    const int n0 = blockIdx.x * 256;
    const int b  = blockIdx.y;
    const int i  = blockIdx.z;

    for (int idx = t; idx < NDIM * NHID; idx += 256)
        sw1[idx] = fW1[i * NDIM * NHID + idx];
    if (t < NHID) sfb1[t] = fb1[i * NHID + t];

    const int ht8 = (t & 3) * 8;
    const int nb  = (t >> 2) * 4;
    const float4* src4 =
        reinterpret_cast<const float4*>(data + ((size_t)b * NVEC + n0) * NDIM);

    // thread stages 2 float4 per chunk: p = t, t+256 -> row = p>>1, sub = p&1
    const int srow0 = t >> 1,            ssub0 = t & 1;
    const int srow1 = (t + 256) >> 1,    ssub1 = t & 1;   // (t+256)&1 == t&1

    unsigned long long acc[4][4];
#pragma unroll
    for (int j = 0; j < 4; j++)
#pragma unroll
        for (int p = 0; p < 4; p++) acc[j][p] = 0ull;

    // prologue: stage chunk 0 into buf 0
    {
        float4 v0 = __ldg(src4 + srow0 * 16 + ssub0);
        float4 v1 = __ldg(src4 + srow1 * 16 + ssub1);
        float* d0 = Xs + srow0 * XS + ssub0 * 4;
        float* d1 = Xs + srow1 * XS + ssub1 * 4;
        d0[0] = v0.x; d0[1] = v0.y; d0[2] = v0.z; d0[3] = v0.w;
        d1[0] = v1.x; d1[1] = v1.y; d1[2] = v1.z; d1[3] = v1.w;
    }
    __syncthreads();

#pragma unroll 1
    for (int c = 0; c < 8; c++) {
        float4 v0, v1;
        if (c < 7) {                     // issue next chunk's loads NOW
            v0 = __ldg(src4 + srow0 * 16 + (c + 1) * 2 + ssub0);
            v1 = __ldg(src4 + srow1 * 16 + (c + 1) * 2 + ssub1);
        }

        const float* Xb = Xs + (c & 1) * 256 * XS;
#pragma unroll
        for (int kk = 0; kk < 8; kk++) {
            int k = 8 * c + kk;
            const unsigned long long* wp =
                reinterpret_cast<const unsigned long long*>(&sw1[k * NHID + ht8]);
            unsigned long long w0 = wp[0], w1 = wp[1], w2 = wp[2], w3 = wp[3];
#pragma unroll
            for (int j = 0; j < 4; j++) {
                float xv = Xb[(nb + j) * XS + kk];
                unsigned long long xx = pack2(xv, xv);
                fma2(acc[j][0], xx, w0);
                fma2(acc[j][1], xx, w1);
                fma2(acc[j][2], xx, w2);
                fma2(acc[j][3], xx, w3);
            }
        }

        if (c < 7) {                     // data arrived during compute
            float* Xn = Xs + ((c + 1) & 1) * 256 * XS;
            float* d0 = Xn + srow0 * XS + ssub0 * 4;
            float* d1 = Xn + srow1 * XS + ssub1 * 4;
            d0[0] = v0.x; d0[1] = v0.y; d0[2] = v0.z; d0[3] = v0.w;
            d1[0] = v1.x; d1[1] = v1.y; d1[2] = v1.z; d1[3] = v1.w;
        }
        __syncthreads();
    }

    const unsigned long long* bp =
        reinterpret_cast<const unsigned long long*>(&sfb1[ht8]);
    float2 bb[4];
#pragma unroll
    for (int p = 0; p < 4; p++) bb[p] = unpack2(bp[p]);

    float* Hbase = g_H + ((size_t)(i * NB + b) * NVEC) * NHID;
#pragma unroll
    for (int j = 0; j < 4; j++) {
        float2 v0 = unpack2(acc[j][0]);
        float2 v1 = unpack2(acc[j][1]);
        float2 v2 = unpack2(acc[j][2]);
        float2 v3 = unpack2(acc[j][3]);
        float4 a = make_float4(gelu_exact(v0.x + bb[0].x), gelu_exact(v0.y + bb[0].y),
                               gelu_exact(v1.x + bb[1].x), gelu_exact(v1.y + bb[1].y));
        float4 cc = make_float4(gelu_exact(v2.x + bb[2].x), gelu_exact(v2.y + bb[2].y),
                                gelu_exact(v3.x + bb[3].x), gelu_exact(v3.y + bb[3].y));
        float* dst = Hbase + (size_t)(n0 + nb + j) * NHID + ht8;
        reinterpret_cast<float4*>(dst)[0] = a;
        reinterpret_cast<float4*>(dst)[1] = cc;
    }
}

// ---------------------------------------------------------------------------
// Kernel B: sparse W values. Block = (b, i), 1024 threads (t = n), 160 blocks.
// ---------------------------------------------------------------------------
#define FTS 36
#define W2_SMEM ((NVEC * FTS + NVEC) * 4)   // 151552 B

__global__ void __launch_bounds__(1024) w2_kernel(const float* __restrict__ fb2)
{
    extern __shared__ float sm[];
    float* sfT  = sm;              // [1024][36]
    float* sfb2 = sm + NVEC * FTS; // [1024]

    const int t = threadIdx.x;
    const int b = blockIdx.x;
    const int i = blockIdx.y;

    const float4* src4 =
        reinterpret_cast<const float4*>(g_fW2T + (size_t)i * NVEC * NHID);
#pragma unroll
    for (int q = 0; q < 8; q++) {
        int p = t + 1024 * q;
        float4 v = src4[p];
        int n = p >> 3, c = (p & 7) << 2;
        *reinterpret_cast<float4*>(&sfT[n * FTS + c]) = v;
    }
    sfb2[t] = __ldg(&fb2[i * NVEC + t]);

    float h[32];
    {
        const float4* hp = reinterpret_cast<const float4*>(
            g_H + ((size_t)(i * NB + b) * NVEC + t) * NHID);
#pragma unroll
        for (int q = 0; q < 8; q++) {
            float4 v = __ldg(hp + q);
            h[4 * q] = v.x; h[4 * q + 1] = v.y; h[4 * q + 2] = v.z; h[4 * q + 3] = v.w;
        }
    }
    __syncthreads();

    const int OFF[NOFF] = {0, 1, 2, 4, 8, 16, 32, 64, 128, 256, 512};
    float* out = g_w + (size_t)((i * NB + b) * NOFF) * NVEC + t;
#pragma unroll
    for (int o = 0; o < NOFF; o++) {
        int m = (t + OFF[o]) & (NVEC - 1);
        const float4* rp = reinterpret_cast<const float4*>(&sfT[m * FTS]);
        float s0 = 0.f, s1 = 0.f, s2 = 0.f, s3 = 0.f;
#pragma unroll
        for (int q = 0; q < 8; q++) {
            float4 w = rp[q];
            s0 = fmaf(h[4 * q],     w.x, s0);
            s1 = fmaf(h[4 * q + 1], w.y, s1);
            s2 = fmaf(h[4 * q + 2], w.z, s2);
            s3 = fmaf(h[4 * q + 3], w.w, s3);
        }
        out[(size_t)o * NVEC] = (s0 + s1) + (s2 + s3) + sfb2[m];
    }
}

// ---------------------------------------------------------------------------
// Kernel 2: 10-layer sparse recursion, vectorized (block = (dg,b) owns 4 dims
// as float4). 256 blocks, 2 CTAs/SM. Fused output-GEMM epilogue.
// ---------------------------------------------------------------------------
__global__ void __launch_bounds__(1024, 2) recurse_kernel(
    const float* __restrict__ data, const float* __restrict__ finb,
    float* __restrict__ out)
{
    __shared__ float4 Vs[2][NVEC];
    __shared__ int isLast;
    const int t  = threadIdx.x;
    const int dg = blockIdx.x;
    const int b  = blockIdx.y;

    float4 acc = __ldg(reinterpret_cast<const float4*>(
        data + ((size_t)(b * NVEC) + t) * NDIM + 4 * dg));
    Vs[0][t] = acc;

    const int OFF[NOFF] = {0, 1, 2, 4, 8, 16, 32, 64, 128, 256, 512};
    float wv[NOFF];
    {
        const float* w = g_w + (size_t)((9 * NB + b) * NOFF) * NVEC;
#pragma unroll
        for (int o = 0; o < NOFF; o++) wv[o] = __ldg(&w[o * NVEC + t]);
    }
    __syncthreads();

    int cur = 0;
#pragma unroll
    for (int i = NW - 1; i >= 0; i--) {
        float wn[NOFF];
        if (i > 0) {
            const float* w = g_w + (size_t)(((i - 1) * NB + b) * NOFF) * NVEC;
#pragma unroll
            for (int o = 0; o < NOFF; o++) wn[o] = __ldg(&w[o * NVEC + t]);
        }

        float4 na;
        na.x = fmaf(wv[0], acc.x, acc.x);
        na.y = fmaf(wv[0], acc.y, acc.y);
        na.z = fmaf(wv[0], acc.z, acc.z);
        na.w = fmaf(wv[0], acc.w, acc.w);
#pragma unroll
        for (int o = 1; o < NOFF; o++) {
            int m = (t + OFF[o]) & (NVEC - 1);
            float4 v = Vs[cur][m];
            na.x = fmaf(wv[o], v.x, na.x);
            na.y = fmaf(wv[o], v.y, na.y);
            na.z = fmaf(wv[o], v.z, na.z);
            na.w = fmaf(wv[o], v.w, na.w);
        }
        Vs[cur ^ 1][t] = na;
        acc = na;
        __syncthreads();
        cur ^= 1;
#pragma unroll
        for (int o = 0; o < NOFF; o++) wv[o] = wn[o];
    }

    const float4* W3 = reinterpret_cast<const float4*>(g_fWT3);
    float cs[10];
#pragma unroll
    for (int c = 0; c < 10; c++) {
        float4 w = __ldg(&W3[(c * 16 + dg) * 1024 + t]);
        cs[c] = acc.x * w.x + acc.y * w.y + acc.z * w.z + acc.w * w.w;
    }

#pragma unroll
    for (int c = 0; c < 10; c++) {
#pragma unroll
        for (int s = 16; s > 0; s >>= 1)
            cs[c] += __shfl_xor_sync(0xffffffffu, cs[c], s);
    }
    float* red = reinterpret_cast<float*>(&Vs[0][0]);
    int lane = t & 31, wp = t >> 5;
    if (lane == 0) {
#pragma unroll
        for (int c = 0; c < 10; c++) red[wp * 10 + c] = cs[c];
    }
    __syncthreads();
    if (t < 10) {
        float s = 0.f;
        for (int w_ = 0; w_ < 32; w_++) s += red[w_ * 10 + t];
        g_part[(b * 16 + dg) * 10 + t] = s;
    }
    __threadfence();
    if (t == 0) {
        int old = atomicAdd(&g_cnt, 1);
        isLast = (old == NB * 16 - 1);
    }
    __syncthreads();
    if (isLast) {
        __threadfence();
        if (t == 0) g_cnt = 0;
        if (t < NB * 10) {
            int bb = t / 10, c = t - bb * 10;
            float s = __ldg(&finb[c]);
#pragma unroll
            for (int cc = 0; cc < 16; cc++) s += g_part[(bb * 16 + cc) * 10 + c];
            out[t] = s;
        }
    }
}

// ---------------------------------------------------------------------------
extern "C" void kernel_launch(void* const* d_in, const int* in_sizes, int n_in,
                              void* d_out, int out_size)
{
    const float* data = (const float*)d_in[0];
    const float* fW1  = (const float*)d_in[1];
    const float* fb1  = (const float*)d_in[2];
    const float* fW2  = (const float*)d_in[3];
    const float* fb2  = (const float*)d_in[4];
    const float* finW = (const float*)d_in[5];
    const float* finb = (const float*)d_in[6];
    float* out = (float*)d_out;

    cudaFuncSetAttribute(h_kernel,
                         cudaFuncAttributeMaxDynamicSharedMemorySize, H_SMEM);
    cudaFuncSetAttribute(w2_kernel,
                         cudaFuncAttributeMaxDynamicSharedMemorySize, W2_SMEM);

    prep_kernel<<<52, 256>>>(fW2, finW);
    h_kernel<<<dim3(4, 16, 10), 256, H_SMEM>>>(data, fW1, fb1);
    w2_kernel<<<dim3(16, 10), 1024, W2_SMEM>>>(fb2);
    recurse_kernel<<<dim3(16, 16), 1024>>>(data, finb, out);
}

// round 11
// speedup vs baseline: 1.2878x; 1.2878x over previous
#include <cuda_runtime.h>
#include <cstdint>
#include <cstddef>

#define NVEC 1024
#define NDIM 64
#define NHID 32
#define NW   10
#define NB   16
#define NOFF 11

// Scratch (no allocations allowed): device globals.
// g_w layout: [i][b][og(3)][n][4]  (11 offsets padded to 12, grouped by 4)
__device__ float g_w[NW * NB * 3 * NVEC * 4];
__device__ float g_H[NW * NB * NVEC * NHID];   // gelu hidden activations (21MB)
__device__ float g_fW2T[NW * NVEC * NHID];     // fW2 transposed [i][n][h]
__device__ float g_fWT3[10 * 16 * NVEC * 4];   // finW as [c][dg][n][4] (2.6MB)
__device__ float g_part[NB * 16 * 10];         // partial sums for output GEMM
__device__ int   g_cnt;                        // block completion counter

// ---------- f32x2 packed helpers (sm_103a FFMA2) ----------
__device__ __forceinline__ unsigned long long pack2(float x, float y) {
    unsigned long long r;
    asm("mov.b64 %0, {%1, %2};" : "=l"(r) : "f"(x), "f"(y));
    return r;
}
__device__ __forceinline__ void fma2(unsigned long long& d, unsigned long long a, unsigned long long b) {
    asm("fma.rn.f32x2 %0, %1, %2, %0;" : "+l"(d) : "l"(a), "l"(b));
}
__device__ __forceinline__ float2 unpack2(unsigned long long v) {
    float lo, hi;
    asm("mov.b64 {%0, %1}, %2;" : "=f"(lo), "=f"(hi) : "l"(v));
    return make_float2(lo, hi);
}
__device__ __forceinline__ float gelu_exact(float x) {
    return 0.5f * x * (1.0f + erff(x * 0.70710678f));
}

// ---------------------------------------------------------------------------
// Kernel A: H = gelu(X @ fW1 + fb1), 4n x 8h register tile, 256 threads,
// k CHUNKED (4 x 16) -> Xs[256][17], 25.7KB smem, 4 CTAs/SM.
// w1 rows read as LDS.128 (ulonglong2) -> 2 instr/1wf each instead of 4 LDS.64.
// z == 10: transpose fW2 -> g_fW2T.   z == 11: finW -> g_fWT3 (4 sub-tiles).
// ---------------------------------------------------------------------------
#define XS 17
#define H_SMEM ((256 * XS + NDIM * NHID + NHID) * 4)   // 25728 B

__global__ void __launch_bounds__(256, 4) h_kernel(
    const float* __restrict__ data, const float* __restrict__ fW1,
    const float* __restrict__ fb1,  const float* __restrict__ fW2,
    const float* __restrict__ finW)
{
    extern __shared__ float sm[];
    const int t = threadIdx.x;

    // ---------------- fW2 transpose branch ----------------
    if (blockIdx.z == NW) {
        int idx = blockIdx.y * 4 + blockIdx.x;     // 0..63
        if (idx >= 2 * NW) return;
        const int i  = idx >> 1;
        const int c0 = (idx & 1) * 512;
        float* tile = sm;                          // [32][33]
        for (int s = 0; s < 16; s++) {
#pragma unroll
            for (int it = 0; it < 4; it++) {
                int r = it * 8 + (t >> 5);
                int c = t & 31;
                if (r < 32)
                    tile[r * 33 + c] = fW2[((size_t)(i * NHID) + r) * NVEC + c0 + s * 32 + c];
            }
            __syncthreads();
            int cr = t >> 3, rg = t & 7;
            float4 v = make_float4(tile[(4 * rg + 0) * 33 + cr],
                                   tile[(4 * rg + 1) * 33 + cr],
                                   tile[(4 * rg + 2) * 33 + cr],
                                   tile[(4 * rg + 3) * 33 + cr]);
            *reinterpret_cast<float4*>(
                &g_fW2T[((size_t)(i * NVEC) + c0 + s * 32 + cr) * NHID + 4 * rg]) = v;
            __syncthreads();
        }
        return;
    }

    // ------------- finW transpose branch: [f][10] -> [c][dg][n][4] ----------
    if (blockIdx.z == NW + 1) {
        int idx = blockIdx.y * 4 + blockIdx.x;     // 0..63
        float* sF = sm;                            // [256][11]
        float4* dst = reinterpret_cast<float4*>(g_fWT3);
#pragma unroll 1
        for (int s = 0; s < 4; s++) {
            const int fbase = idx * 1024 + s * 256;
            const int nbase = (idx * 16) + s * 4;
            const float4* src =
                reinterpret_cast<const float4*>(finW + (size_t)fbase * 10);
#pragma unroll
            for (int j = 0; j < 3; j++) {
                int p = t + 256 * j;
                if (p < 640) {
                    float4 v = __ldg(src + p);
                    float vals[4] = {v.x, v.y, v.z, v.w};
#pragma unroll
                    for (int u = 0; u < 4; u++) {
                        int e  = 4 * p + u;
                        int fl = e / 10, c = e - 10 * fl;
                        sF[fl * 11 + c] = vals[u];
                    }
                }
            }
            __syncthreads();
#pragma unroll
            for (int j = 0; j < 3; j++) {
                int oi = t + 256 * j;
                if (oi < 640) {
                    int c  = oi / 64;
                    int r  = oi - 64 * c;
                    int dg = r >> 2, nn = r & 3;
                    float4 v;
                    v.x = sF[(nn * 64 + 4 * dg + 0) * 11 + c];
                    v.y = sF[(nn * 64 + 4 * dg + 1) * 11 + c];
                    v.z = sF[(nn * 64 + 4 * dg + 2) * 11 + c];
                    v.w = sF[(nn * 64 + 4 * dg + 3) * 11 + c];
                    dst[(c * 16 + dg) * 1024 + nbase + nn] = v;
                }
            }
            __syncthreads();
        }
        return;
    }

    // ---------------- H branch ----------------
    float* Xs   = sm;                   // [256][17]
    float* sw1  = Xs + 256 * XS;        // [64][32]
    float* sfb1 = sw1 + NDIM * NHID;    // [32]

    const int n0 = blockIdx.x * 256;
    const int b  = blockIdx.y;
    const int i  = blockIdx.z;

    for (int idx = t; idx < NDIM * NHID; idx += 256)
        sw1[idx] = fW1[i * NDIM * NHID + idx];
    if (t < NHID) sfb1[t] = fb1[i * NHID + t];

    const int ht8 = (t & 3) * 8;
    const int nb  = (t >> 2) * 4;
    const float4* src =
        reinterpret_cast<const float4*>(data + ((size_t)b * NVEC + n0) * NDIM);

    unsigned long long acc[4][4];
#pragma unroll
    for (int j = 0; j < 4; j++)
#pragma unroll
        for (int p = 0; p < 4; p++) acc[j][p] = 0ull;

#pragma unroll 1
    for (int c = 0; c < 4; c++) {
#pragma unroll
        for (int j = 0; j < 4; j++) {
            int q   = t + 256 * j;
            int row = q >> 2, sub = q & 3;
            float4 v = __ldg(src + row * 16 + c * 4 + sub);
            float* d = Xs + row * XS + sub * 4;
            d[0] = v.x; d[1] = v.y; d[2] = v.z; d[3] = v.w;
        }
        __syncthreads();

#pragma unroll
        for (int kk = 0; kk < 16; kk++) {
            int k = 16 * c + kk;
            const ulonglong2* wp =
                reinterpret_cast<const ulonglong2*>(&sw1[k * NHID + ht8]);
            ulonglong2 wA = wp[0];            // LDS.128: w pair 0,1
            ulonglong2 wB = wp[1];            // LDS.128: w pair 2,3
#pragma unroll
            for (int j = 0; j < 4; j++) {
                float xv = Xs[(nb + j) * XS + kk];
                unsigned long long xx = pack2(xv, xv);
                fma2(acc[j][0], xx, wA.x);
                fma2(acc[j][1], xx, wA.y);
                fma2(acc[j][2], xx, wB.x);
                fma2(acc[j][3], xx, wB.y);
            }
        }
        if (c < 3) __syncthreads();
    }

    const unsigned long long* bp =
        reinterpret_cast<const unsigned long long*>(&sfb1[ht8]);
    float2 bb[4];
#pragma unroll
    for (int p = 0; p < 4; p++) bb[p] = unpack2(bp[p]);

    float* Hbase = g_H + ((size_t)(i * NB + b) * NVEC) * NHID;
#pragma unroll
    for (int j = 0; j < 4; j++) {
        float2 v0 = unpack2(acc[j][0]);
        float2 v1 = unpack2(acc[j][1]);
        float2 v2 = unpack2(acc[j][2]);
        float2 v3 = unpack2(acc[j][3]);
        float4 a = make_float4(gelu_exact(v0.x + bb[0].x), gelu_exact(v0.y + bb[0].y),
                               gelu_exact(v1.x + bb[1].x), gelu_exact(v1.y + bb[1].y));
        float4 cc = make_float4(gelu_exact(v2.x + bb[2].x), gelu_exact(v2.y + bb[2].y),
                                gelu_exact(v3.x + bb[3].x), gelu_exact(v3.y + bb[3].y));
        float* dst = Hbase + (size_t)(n0 + nb + j) * NHID + ht8;
        reinterpret_cast<float4*>(dst)[0] = a;
        reinterpret_cast<float4*>(dst)[1] = cc;
    }
}

// ---------------------------------------------------------------------------
// Kernel B: sparse W values. Block = (b, i), 1024 threads (t = n), 160 blocks.
// Results gathered in registers, then written as 3 coalesced STG.128.
// ---------------------------------------------------------------------------
#define FTS 36
#define W2_SMEM ((NVEC * FTS + NVEC) * 4)   // 151552 B

__global__ void __launch_bounds__(1024) w2_kernel(const float* __restrict__ fb2)
{
    extern __shared__ float sm[];
    float* sfT  = sm;              // [1024][36]
    float* sfb2 = sm + NVEC * FTS; // [1024]

    const int t = threadIdx.x;
    const int b = blockIdx.x;
    const int i = blockIdx.y;

    const float4* src4 =
        reinterpret_cast<const float4*>(g_fW2T + (size_t)i * NVEC * NHID);
#pragma unroll
    for (int q = 0; q < 8; q++) {
        int p = t + 1024 * q;
        float4 v = src4[p];
        int n = p >> 3, c = (p & 7) << 2;
        *reinterpret_cast<float4*>(&sfT[n * FTS + c]) = v;
    }
    sfb2[t] = __ldg(&fb2[i * NVEC + t]);

    float h[32];
    {
        const float4* hp = reinterpret_cast<const float4*>(
            g_H + ((size_t)(i * NB + b) * NVEC + t) * NHID);
#pragma unroll
        for (int q = 0; q < 8; q++) {
            float4 v = __ldg(hp + q);
            h[4 * q] = v.x; h[4 * q + 1] = v.y; h[4 * q + 2] = v.z; h[4 * q + 3] = v.w;
        }
    }
    __syncthreads();

    const int OFF[NOFF] = {0, 1, 2, 4, 8, 16, 32, 64, 128, 256, 512};
    float wres[12];
#pragma unroll
    for (int o = 0; o < NOFF; o++) {
        int m = (t + OFF[o]) & (NVEC - 1);
        const float4* rp = reinterpret_cast<const float4*>(&sfT[m * FTS]);
        float s0 = 0.f, s1 = 0.f, s2 = 0.f, s3 = 0.f;
#pragma unroll
        for (int q = 0; q < 8; q++) {
            float4 w = rp[q];
            s0 = fmaf(h[4 * q],     w.x, s0);
            s1 = fmaf(h[4 * q + 1], w.y, s1);
            s2 = fmaf(h[4 * q + 2], w.z, s2);
            s3 = fmaf(h[4 * q + 3], w.w, s3);
        }
        wres[o] = (s0 + s1) + (s2 + s3) + sfb2[m];
    }
    wres[11] = 0.f;

    // 3 coalesced STG.128 to g_w[i][b][og][t][4]
    float4* dst = reinterpret_cast<float4*>(g_w) + ((size_t)(i * NB + b) * 3) * NVEC + t;
    dst[0]        = make_float4(wres[0], wres[1], wres[2],  wres[3]);
    dst[NVEC]     = make_float4(wres[4], wres[5], wres[6],  wres[7]);
    dst[2 * NVEC] = make_float4(wres[8], wres[9], wres[10], wres[11]);
}

// ---------------------------------------------------------------------------
// Kernel 2: 10-layer sparse recursion, vectorized (block = (dg,b) owns 4 dims
// as float4). 256 blocks, 2 CTAs/SM. Per-layer w fetch = 3 coalesced LDG.128
// (prefetched one layer ahead). Fused output-GEMM epilogue.
// ---------------------------------------------------------------------------
__global__ void __launch_bounds__(1024, 2) recurse_kernel(
    const float* __restrict__ data, const float* __restrict__ finb,
    float* __restrict__ out)
{
    __shared__ float4 Vs[2][NVEC];
    __shared__ int isLast;
    const int t  = threadIdx.x;
    const int dg = blockIdx.x;
    const int b  = blockIdx.y;

    float4 acc = __ldg(reinterpret_cast<const float4*>(
        data + ((size_t)(b * NVEC) + t) * NDIM + 4 * dg));
    Vs[0][t] = acc;

    const int OFF[NOFF] = {0, 1, 2, 4, 8, 16, 32, 64, 128, 256, 512};
    const float4* Wv = reinterpret_cast<const float4*>(g_w);

    float4 wq0, wq1, wq2;
    {
        size_t base = ((size_t)(9 * NB + b) * 3) * NVEC + t;
        wq0 = __ldg(&Wv[base]);
        wq1 = __ldg(&Wv[base + NVEC]);
        wq2 = __ldg(&Wv[base + 2 * NVEC]);
    }
    __syncthreads();

    int cur = 0;
#pragma unroll
    for (int i = NW - 1; i >= 0; i--) {
        float4 nq0, nq1, nq2;
        if (i > 0) {
            size_t base = ((size_t)((i - 1) * NB + b) * 3) * NVEC + t;
            nq0 = __ldg(&Wv[base]);
            nq1 = __ldg(&Wv[base + NVEC]);
            nq2 = __ldg(&Wv[base + 2 * NVEC]);
        }
        float wv[NOFF] = {wq0.x, wq0.y, wq0.z, wq0.w,
                          wq1.x, wq1.y, wq1.z, wq1.w,
                          wq2.x, wq2.y, wq2.z};

        float4 na;
        na.x = fmaf(wv[0], acc.x, acc.x);
        na.y = fmaf(wv[0], acc.y, acc.y);
        na.z = fmaf(wv[0], acc.z, acc.z);
        na.w = fmaf(wv[0], acc.w, acc.w);
#pragma unroll
        for (int o = 1; o < NOFF; o++) {
            int m = (t + OFF[o]) & (NVEC - 1);
            float4 v = Vs[cur][m];
            na.x = fmaf(wv[o], v.x, na.x);
            na.y = fmaf(wv[o], v.y, na.y);
            na.z = fmaf(wv[o], v.z, na.z);
            na.w = fmaf(wv[o], v.w, na.w);
        }
        Vs[cur ^ 1][t] = na;
        acc = na;
        __syncthreads();
        cur ^= 1;
        wq0 = nq0; wq1 = nq1; wq2 = nq2;
    }

    const float4* W3 = reinterpret_cast<const float4*>(g_fWT3);
    float cs[10];
#pragma unroll
    for (int c = 0; c < 10; c++) {
        float4 w = __ldg(&W3[(c * 16 + dg) * 1024 + t]);
        cs[c] = acc.x * w.x + acc.y * w.y + acc.z * w.z + acc.w * w.w;
    }

#pragma unroll
    for (int c = 0; c < 10; c++) {
#pragma unroll
        for (int s = 16; s > 0; s >>= 1)
            cs[c] += __shfl_xor_sync(0xffffffffu, cs[c], s);
    }
    float* red = reinterpret_cast<float*>(&Vs[0][0]);
    int lane = t & 31, wp = t >> 5;
    if (lane == 0) {
#pragma unroll
        for (int c = 0; c < 10; c++) red[wp * 10 + c] = cs[c];
    }
    __syncthreads();
    if (t < 10) {
        float s = 0.f;
        for (int w_ = 0; w_ < 32; w_++) s += red[w_ * 10 + t];
        g_part[(b * 16 + dg) * 10 + t] = s;
    }
    __threadfence();
    if (t == 0) {
        int old = atomicAdd(&g_cnt, 1);
        isLast = (old == NB * 16 - 1);
    }
    __syncthreads();
    if (isLast) {
        __threadfence();
        if (t == 0) g_cnt = 0;
        if (t < NB * 10) {
            int bb = t / 10, c = t - bb * 10;
            float s = __ldg(&finb[c]);
#pragma unroll
            for (int cc = 0; cc < 16; cc++) s += g_part[(bb * 16 + cc) * 10 + c];
            out[t] = s;
        }
    }
}

// ---------------------------------------------------------------------------
extern "C" void kernel_launch(void* const* d_in, const int* in_sizes, int n_in,
                              void* d_out, int out_size)
{
    const float* data = (const float*)d_in[0];
    const float* fW1  = (const float*)d_in[1];
    const float* fb1  = (const float*)d_in[2];
    const float* fW2  = (const float*)d_in[3];
    const float* fb2  = (const float*)d_in[4];
    const float* finW = (const float*)d_in[5];
    const float* finb = (const float*)d_in[6];
    float* out = (float*)d_out;

    cudaFuncSetAttribute(h_kernel,
                         cudaFuncAttributeMaxDynamicSharedMemorySize, H_SMEM);
    cudaFuncSetAttribute(w2_kernel,
                         cudaFuncAttributeMaxDynamicSharedMemorySize, W2_SMEM);

    h_kernel<<<dim3(4, 16, 12), 256, H_SMEM>>>(data, fW1, fb1, fW2, finW);
    w2_kernel<<<dim3(16, 10), 1024, W2_SMEM>>>(fb2);
    recurse_kernel<<<dim3(16, 16), 1024>>>(data, finb, out);
}